// round 9
// baseline (speedup 1.0000x reference)
#include <cuda_runtime.h>
#include <cuda_bf16.h>
#include <cstdint>
#include <math.h>

// ============================================================
// DocAttention on GB300 — single persistent kernel.
//   logits[b,x] = Q[b,x]·(Σ_a K[b,a]) − Q[b,x]·K[b,x]
//   Q = (cls@Wq + bq)*m, K = (cls@Wk + bk)*m
//   out = softmax(logits + (1−m)·−1e5)
// Phases: A) f32->bf16 converts + W transpose + mask compaction
//         B) mma.sync bf16 GEMM (compacted rows, adaptive split-K)
//         C) reduction partials + last-block softmax
// Grid = 128 CTAs (1 per SM, all resident) -> spin grid barriers.
// ============================================================

#define NCTA 128

__device__ __forceinline__ uint32_t smem_u32(const void* p) {
    uint32_t a;
    asm("{ .reg .u64 t; cvta.to.shared.u64 t, %1; cvt.u32.u64 %0, t; }"
        : "=r"(a) : "l"(p));
    return a;
}

// ---------------- scratch (device globals; no allocation) ----------------
__device__ __align__(16) __nv_bfloat16 g_A[1024 * 1024];     // cls bf16 [m][k]
__device__ __align__(16) __nv_bfloat16 g_B[2048 * 1024];     // [WqT|WkT] bf16 [n][k]
__device__ float g_qkA[1024 * 2048];                          // split 0 raw products
__device__ float g_qkB[1024 * 2048];                          // split 1 raw products
__device__ float g_part[1024 * 8];                            // partial logits
__device__ int   g_rowlist[1024];
__device__ int   g_rowcnt;
__device__ int   g_sync[2];
__device__ int   g_ctr;

// device-wide barrier: all NCTA CTAs are co-resident (1/SM) so spinning is safe
__device__ __forceinline__ void grid_sync(int slot) {
    __syncthreads();
    if (threadIdx.x == 0) {
        __threadfence();
        atomicAdd(&g_sync[slot], 1);
        while (((volatile int*)g_sync)[slot] < NCTA) { }
    }
    __syncthreads();
}

#define BK 64
#define STAGE_BYTES 32768
#define NSTAGE 4
#define DSMEM_BYTES (NSTAGE * STAGE_BYTES)   // 131072; also covers 32x257 f32 transpose tile

__global__ __launch_bounds__(256, 1)
void mega(const float* __restrict__ enc,
          const int*   __restrict__ mask,
          const float* __restrict__ wq,
          const float* __restrict__ bq,
          const float* __restrict__ wk,
          const float* __restrict__ bk,
          float* __restrict__ out) {
    extern __shared__ __align__(1024) char smem[];
    const uint32_t base = smem_u32(smem);
    const int cta = blockIdx.x;
    const int tid = threadIdx.x, warp = tid >> 5, lane = tid & 31;

    __shared__ int   rlTile[128];
    __shared__ float ks[128];
    __shared__ float sm_m[32];
    __shared__ int   isLast;

    // ================= Phase A: converts + transpose + compaction ==========
    // cls: 8 rows per CTA (warp per row)
    {
        const int row = cta * 8 + warp;
        const float4* __restrict__ src =
            reinterpret_cast<const float4*>(enc + (size_t)row * 131072);
        uint2* __restrict__ dst = reinterpret_cast<uint2*>(g_A + (size_t)row * 1024);
        float4 v[8];
        #pragma unroll
        for (int i = 0; i < 8; i++) v[i] = src[lane + 32 * i];
        #pragma unroll
        for (int i = 0; i < 8; i++) {
            __nv_bfloat16 h[4];
            h[0] = __float2bfloat16(v[i].x);
            h[1] = __float2bfloat16(v[i].y);
            h[2] = __float2bfloat16(v[i].z);
            h[3] = __float2bfloat16(v[i].w);
            dst[lane + 32 * i] = *reinterpret_cast<uint2*>(h);
        }
    }
    // W transpose: 2 tiles of 32k x 256n per CTA (256 tiles total)
    {
        float* ts = reinterpret_cast<float*>(smem);    // [32][257]
        #pragma unroll
        for (int t2 = 0; t2 < 2; t2++) {
            const int widx = cta * 2 + t2;             // 0..255
            const int z = widx >> 7;
            const int rest = widx & 127;
            const int kt = rest & 31;
            const int nt = rest >> 5;
            const int k0 = kt * 32, n0 = nt * 256;
            const float* __restrict__ W = z ? wk : wq;

            const int kk = tid >> 6;
            const int n4 = (tid & 63) * 4;
            #pragma unroll
            for (int i = 0; i < 8; i++) {
                const int k = kk + i * 4;
                const float4 v = *reinterpret_cast<const float4*>(
                    W + (size_t)(k0 + k) * 1024 + n0 + n4);
                ts[k * 257 + n4 + 0] = v.x;
                ts[k * 257 + n4 + 1] = v.y;
                ts[k * 257 + n4 + 2] = v.z;
                ts[k * 257 + n4 + 3] = v.w;
            }
            __syncthreads();
            __nv_bfloat16 h[32];
            #pragma unroll
            for (int k = 0; k < 32; k++)
                h[k] = __float2bfloat16(ts[k * 257 + tid]);
            uint4* __restrict__ dst = reinterpret_cast<uint4*>(
                g_B + (size_t)(z * 1024 + n0 + tid) * 1024 + k0);
            #pragma unroll
            for (int i = 0; i < 4; i++)
                dst[i] = reinterpret_cast<uint4*>(h)[i];
            __syncthreads();
        }
    }
    // compaction (CTA 0, warp 0)
    if (cta == 0 && tid < 32) {
        int prev = 0;
        #pragma unroll
        for (int it = 0; it < 32; it++) {
            const int idx = it * 32 + tid;
            const bool v = (mask[idx] != 0);
            const unsigned ball = __ballot_sync(0xFFFFFFFFu, v);
            if (v) g_rowlist[prev + __popc(ball & ((1u << tid) - 1u))] = idx;
            prev += __popc(ball);
        }
        if (tid == 0) g_rowcnt = prev;
    }

    grid_sync(0);

    // ================= Phase B: GEMM over task list ========================
    const int cnt = g_rowcnt;
    const int nM = (cnt + 127) >> 7;
    const int nsplit = (nM <= 4) ? 2 : 1;
    const int nkb = (nsplit == 2) ? 8 : 16;
    const int total = 16 * nM * nsplit;
    const int mw = (warp & 1) * 64;
    const int nw = (warp >> 1) * 32;
    const int lj = lane >> 3;
    const int li = lane & 7;

    for (int task = cta; task < total; task += NCTA) {
        const int bx = task & 15;
        const int rest = task >> 4;
        const int mtile = rest % nM;
        const int split = rest / nM;
        const int mBase = mtile * 128;
        const int nBase = bx * 128;
        const int kOff = split * 8;

        __syncthreads();
        if (tid < 128)
            rlTile[tid] = (mBase + tid < cnt) ? g_rowlist[mBase + tid] : 0;
        __syncthreads();

        float c[4][4][4];
        #pragma unroll
        for (int i = 0; i < 4; i++)
            #pragma unroll
            for (int j = 0; j < 4; j++)
                #pragma unroll
                for (int r = 0; r < 4; r++) c[i][j][r] = 0.f;

        auto issue = [&](int kb) {
            const int stage = kb & (NSTAGE - 1);
            const uint32_t sA = base + (uint32_t)stage * STAGE_BYTES;
            const uint32_t sB = sA + 16384;
            const int k0 = (kOff + kb) * BK;
            #pragma unroll
            for (int i = 0; i < 4; i++) {
                const int idx = i * 256 + tid;
                const int row = idx >> 3, ch = idx & 7;
                const uint32_t swz = (uint32_t)((ch ^ (row & 7)) << 4);
                const __nv_bfloat16* gA =
                    g_A + (size_t)rlTile[row] * 1024 + k0 + ch * 8;
                const __nv_bfloat16* gB =
                    g_B + (size_t)(nBase + row) * 1024 + k0 + ch * 8;
                asm volatile("cp.async.cg.shared.global [%0], [%1], 16;"
                             :: "r"(sA + (uint32_t)row * 128 + swz), "l"(gA));
                asm volatile("cp.async.cg.shared.global [%0], [%1], 16;"
                             :: "r"(sB + (uint32_t)row * 128 + swz), "l"(gB));
            }
            asm volatile("cp.async.commit_group;");
        };

        auto compute = [&](int stage) {
            const uint32_t sA = base + (uint32_t)stage * STAGE_BYTES;
            const uint32_t sB = sA + 16384;
            #pragma unroll
            for (int kc = 0; kc < BK / 16; kc++) {
                uint32_t a[4][4];
                #pragma unroll
                for (int mt = 0; mt < 4; mt++) {
                    const int row = mw + mt * 16 + ((lj & 1) << 3) + li;
                    const int ch = kc * 2 + (lj >> 1);
                    const uint32_t addr =
                        sA + (uint32_t)(row * 128 + ((ch ^ (row & 7)) << 4));
                    asm volatile("ldmatrix.sync.aligned.m8n8.x4.shared.b16 "
                                 "{%0,%1,%2,%3}, [%4];"
                                 : "=r"(a[mt][0]), "=r"(a[mt][1]),
                                   "=r"(a[mt][2]), "=r"(a[mt][3])
                                 : "r"(addr));
                }
                uint32_t b[2][4];
                #pragma unroll
                for (int nh = 0; nh < 2; nh++) {
                    const int row = nw + nh * 16 + ((lj >> 1) << 3) + li;
                    const int ch = kc * 2 + (lj & 1);
                    const uint32_t addr =
                        sB + (uint32_t)(row * 128 + ((ch ^ (row & 7)) << 4));
                    asm volatile("ldmatrix.sync.aligned.m8n8.x4.shared.b16 "
                                 "{%0,%1,%2,%3}, [%4];"
                                 : "=r"(b[nh][0]), "=r"(b[nh][1]),
                                   "=r"(b[nh][2]), "=r"(b[nh][3])
                                 : "r"(addr));
                }
                #pragma unroll
                for (int mt = 0; mt < 4; mt++)
                    #pragma unroll
                    for (int nt = 0; nt < 4; nt++) {
                        const uint32_t b0 = b[nt >> 1][(nt & 1) * 2 + 0];
                        const uint32_t b1 = b[nt >> 1][(nt & 1) * 2 + 1];
                        asm volatile(
                            "mma.sync.aligned.m16n8k16.row.col.f32.bf16.bf16.f32 "
                            "{%0,%1,%2,%3}, {%4,%5,%6,%7}, {%8,%9}, {%0,%1,%2,%3};"
                            : "+f"(c[mt][nt][0]), "+f"(c[mt][nt][1]),
                              "+f"(c[mt][nt][2]), "+f"(c[mt][nt][3])
                            : "r"(a[mt][0]), "r"(a[mt][1]),
                              "r"(a[mt][2]), "r"(a[mt][3]),
                              "r"(b0), "r"(b1));
                    }
            }
        };

        issue(0); issue(1); issue(2);
        for (int kb = 0; kb < nkb; kb++) {
            if (kb < nkb - 2)       asm volatile("cp.async.wait_group 2;");
            else if (kb == nkb - 2) asm volatile("cp.async.wait_group 1;");
            else                    asm volatile("cp.async.wait_group 0;");
            __syncthreads();
            if (kb + 3 < nkb) issue(kb + 3);
            compute(kb & (NSTAGE - 1));
        }

        float* __restrict__ dst = split ? g_qkB : g_qkA;
        #pragma unroll
        for (int mt = 0; mt < 4; mt++) {
            #pragma unroll
            for (int half = 0; half < 2; half++) {
                const int compact = mBase + mw + mt * 16 + (lane >> 2) + half * 8;
                if (compact >= cnt) continue;
                const int orig = rlTile[compact - mBase];
                #pragma unroll
                for (int nt = 0; nt < 4; nt++) {
                    const int col = nBase + nw + nt * 8 + (lane & 3) * 2;
                    float2 v;
                    v.x = c[mt][nt][half * 2 + 0];
                    v.y = c[mt][nt][half * 2 + 1];
                    *reinterpret_cast<float2*>(dst + (size_t)orig * 2048 + col) = v;
                }
            }
        }
    }

    grid_sync(1);

    // ================= Phase C: partials + last-block softmax ==============
    const bool two = (nsplit == 2);
    #pragma unroll
    for (int s = 0; s < 2; s++) {
        const int t = cta * 2 + s;          // 0..255
        const int ds = t & 7;
        const int b  = t >> 3;
        const float* __restrict__ p0 = g_qkA + (size_t)b * 32 * 2048;
        const float* __restrict__ p1 = g_qkB + (size_t)b * 32 * 2048;
        const int d0 = ds * 128;

        __syncthreads();
        if (tid < 32) sm_m[tid] = (float)mask[b * 32 + tid];
        __syncthreads();

        if (tid < 128) {
            const int d = d0 + tid;
            const float bkd = bk[d];
            float ssum = 0.f;
            #pragma unroll
            for (int a = 0; a < 32; a++) {
                float kv = p0[a * 2048 + 1024 + d];
                if (two) kv += p1[a * 2048 + 1024 + d];
                ssum += sm_m[a] * (kv + bkd);
            }
            ks[tid] = ssum;
        }
        __syncthreads();

        const int d = d0 + lane * 4;
        const float4 bqv = *reinterpret_cast<const float4*>(bq + d);
        const float4 bkv = *reinterpret_cast<const float4*>(bk + d);
        const float4 sv = *reinterpret_cast<const float4*>(ks + lane * 4);

        #pragma unroll
        for (int xi = 0; xi < 4; xi++) {
            const int x = warp + xi * 8;
            if (sm_m[x] == 0.f) {
                if (lane == 0) g_part[(b * 32 + x) * 8 + ds] = 0.f;
                continue;
            }
            float4 qv = *reinterpret_cast<const float4*>(p0 + (size_t)x * 2048 + d);
            float4 kv = *reinterpret_cast<const float4*>(p0 + (size_t)x * 2048 + 1024 + d);
            if (two) {
                const float4 qB = *reinterpret_cast<const float4*>(p1 + (size_t)x * 2048 + d);
                const float4 kB = *reinterpret_cast<const float4*>(p1 + (size_t)x * 2048 + 1024 + d);
                qv.x += qB.x; qv.y += qB.y; qv.z += qB.z; qv.w += qB.w;
                kv.x += kB.x; kv.y += kB.y; kv.z += kB.z; kv.w += kB.w;
            }
            float acc;
            acc = (qv.x + bqv.x) * (sv.x - (kv.x + bkv.x));
            acc = fmaf(qv.y + bqv.y, sv.y - (kv.y + bkv.y), acc);
            acc = fmaf(qv.z + bqv.z, sv.z - (kv.z + bkv.z), acc);
            acc = fmaf(qv.w + bqv.w, sv.w - (kv.w + bkv.w), acc);
            #pragma unroll
            for (int o = 16; o > 0; o >>= 1)
                acc += __shfl_xor_sync(0xFFFFFFFFu, acc, o);
            if (lane == 0) g_part[(b * 32 + x) * 8 + ds] = acc;
        }
    }

    __syncthreads();
    if (tid == 0) {
        __threadfence();
        isLast = (atomicAdd(&g_ctr, 1) == NCTA - 1);
    }
    __syncthreads();
    if (!isLast) return;

    // final CTA: reset counters for next replay, then softmax
    if (tid == 0) { g_ctr = 0; g_sync[0] = 0; g_sync[1] = 0; }
    __threadfence();

    #pragma unroll
    for (int p = 0; p < 4; p++) {
        const int b2 = p * 8 + warp;
        float s = 0.f;
        #pragma unroll
        for (int dd = 0; dd < 8; dd++)
            s += g_part[(b2 * 32 + lane) * 8 + dd];
        const float m = (float)mask[b2 * 32 + lane];
        float v = (m != 0.f) ? s : -100000.0f;
        float mx = v;
        #pragma unroll
        for (int o = 16; o > 0; o >>= 1)
            mx = fmaxf(mx, __shfl_xor_sync(0xFFFFFFFFu, mx, o));
        const float e = expf(v - mx);
        float sum = e;
        #pragma unroll
        for (int o = 16; o > 0; o >>= 1)
            sum += __shfl_xor_sync(0xFFFFFFFFu, sum, o);
        out[b2 * 32 + lane] = e / sum;
    }
}

extern "C" void kernel_launch(void* const* d_in, const int* in_sizes, int n_in,
                              void* d_out, int out_size) {
    const float* enc  = (const float*)d_in[0];
    const int*   mask = (const int*)  d_in[1];
    const float* wq   = (const float*)d_in[2];
    const float* bq   = (const float*)d_in[3];
    const float* wk   = (const float*)d_in[4];
    const float* bk   = (const float*)d_in[5];
    float* out = (float*)d_out;

    cudaFuncSetAttribute(mega, cudaFuncAttributeMaxDynamicSharedMemorySize,
                         DSMEM_BYTES);
    mega<<<NCTA, 256, DSMEM_BYTES>>>(enc, mask, wq, bq, wk, bk, out);
}